// round 10
// baseline (speedup 1.0000x reference)
#include <cuda_runtime.h>
#include <cuda_fp16.h>
#include <stdint.h>

#define N_NODES 50000
#define N_EDGES 800000
#define IN_F    128
#define OUT_F   64

#define SA_STRIDE 136   // halves per smem row (128 + 8 pad -> conflict-free frags)
#define SH_STRIDE 72    // halves per epilogue staging row (64 + 8 pad)

#define EPB 64          // edges per batch (scatter)
#define NBATCH 4        // batches per block -> 256 edges/block

// Scratch (allocation-free rule: __device__ globals)
__device__ __half g_h[(size_t)N_NODES * OUT_F];  // 6.4 MB fp16 h table (L2-resident)

// ---------------------------------------------------------------------------
// GEMM: h = feat @ W^T + b  via mma.sync m16n8k16 (fp16 in, fp32 accum).
// (unchanged — smem-staged coalesced epilogue). Side-job: zero `out`.
// ---------------------------------------------------------------------------
__global__ __launch_bounds__(256) void gemm_kernel(
    const float* __restrict__ feat,
    const float* __restrict__ W,
    const float* __restrict__ b,
    float4* __restrict__ out4)
{
    __shared__ __align__(16) __half sA[64 * SA_STRIDE];
    __shared__ __align__(16) __half sB[64 * SA_STRIDE];
    __shared__ float sBias[OUT_F];

    const int tid = threadIdx.x;
    const int node0 = blockIdx.x * 64;

    // Zero the output (independent side-job)
    {
        const int per_blk = (N_NODES * OUT_F / 4 + gridDim.x - 1) / gridDim.x;
        int base = blockIdx.x * per_blk;
        for (int i = tid; i < per_blk; i += 256) {
            int idx = base + i;
            if (idx < N_NODES * OUT_F / 4)
                out4[idx] = make_float4(0.f, 0.f, 0.f, 0.f);
        }
    }

    if (tid < OUT_F) sBias[tid] = b[tid];

    // Load W [64 x 128] fp32 -> fp16 smem
    {
        const float4* src = (const float4*)W;
        #pragma unroll
        for (int i = 0; i < 8; i++) {
            int idx = tid + i * 256;
            int o = idx >> 5, c4 = idx & 31;
            float4 v = src[idx];
            __half2 h01 = __floats2half2_rn(v.x, v.y);
            __half2 h23 = __floats2half2_rn(v.z, v.w);
            uint2 pk;
            pk.x = *(const unsigned int*)&h01;
            pk.y = *(const unsigned int*)&h23;
            *(uint2*)&sB[o * SA_STRIDE + c4 * 4] = pk;
        }
    }
    // Load 64 feat rows fp32 -> fp16 smem, zero-pad past N_NODES
    {
        const float4* src = (const float4*)feat;
        #pragma unroll
        for (int i = 0; i < 8; i++) {
            int idx = tid + i * 256;
            int n = idx >> 5, c4 = idx & 31;
            int node = node0 + n;
            float4 v = (node < N_NODES) ? src[(size_t)node * 32 + c4]
                                        : make_float4(0.f, 0.f, 0.f, 0.f);
            __half2 h01 = __floats2half2_rn(v.x, v.y);
            __half2 h23 = __floats2half2_rn(v.z, v.w);
            uint2 pk;
            pk.x = *(const unsigned int*)&h01;
            pk.y = *(const unsigned int*)&h23;
            *(uint2*)&sA[n * SA_STRIDE + c4 * 4] = pk;
        }
    }
    __syncthreads();

    const int lane = tid & 31;
    const int w    = tid >> 5;
    const int g    = lane >> 2;
    const int t    = lane & 3;
    const int mrow = (w >> 1) * 16;
    const int nbase = (w & 1) * 32;

    float c[4][4] = {};

    #pragma unroll
    for (int ks = 0; ks < 8; ks++) {
        const int k0 = ks * 16;
        const uint32_t a0 = *(const uint32_t*)&sA[(mrow + g    ) * SA_STRIDE + k0 + 2 * t];
        const uint32_t a1 = *(const uint32_t*)&sA[(mrow + g + 8) * SA_STRIDE + k0 + 2 * t];
        const uint32_t a2 = *(const uint32_t*)&sA[(mrow + g    ) * SA_STRIDE + k0 + 2 * t + 8];
        const uint32_t a3 = *(const uint32_t*)&sA[(mrow + g + 8) * SA_STRIDE + k0 + 2 * t + 8];
        #pragma unroll
        for (int nc = 0; nc < 4; nc++) {
            const int n = nbase + nc * 8 + g;
            const uint32_t b0 = *(const uint32_t*)&sB[n * SA_STRIDE + k0 + 2 * t];
            const uint32_t b1 = *(const uint32_t*)&sB[n * SA_STRIDE + k0 + 2 * t + 8];
            asm volatile(
                "mma.sync.aligned.m16n8k16.row.col.f32.f16.f16.f32 "
                "{%0,%1,%2,%3}, {%4,%5,%6,%7}, {%8,%9}, {%0,%1,%2,%3};"
                : "+f"(c[nc][0]), "+f"(c[nc][1]), "+f"(c[nc][2]), "+f"(c[nc][3])
                : "r"(a0), "r"(a1), "r"(a2), "r"(a3), "r"(b0), "r"(b1));
        }
    }

    // Epilogue: stage to smem (conflict-free), then coalesced uint4 STG
    __syncthreads();
    __half* sH = sA;
    #pragma unroll
    for (int nc = 0; nc < 4; nc++) {
        const int col = nbase + nc * 8 + 2 * t;
        const float b0f = sBias[col], b1f = sBias[col + 1];
        const __half2 h0 = __floats2half2_rn(c[nc][0] + b0f, c[nc][1] + b1f);
        const __half2 h1 = __floats2half2_rn(c[nc][2] + b0f, c[nc][3] + b1f);
        *(__half2*)&sH[(mrow + g    ) * SH_STRIDE + col] = h0;
        *(__half2*)&sH[(mrow + g + 8) * SH_STRIDE + col] = h1;
    }
    __syncthreads();
    #pragma unroll
    for (int i = 0; i < 2; i++) {
        int idx = tid + i * 256;
        int row = idx >> 3;
        int c16 = idx & 7;
        int node = node0 + row;
        if (node < N_NODES) {
            uint4 v = *(const uint4*)&sH[row * SH_STRIDE + c16 * 8];
            *(uint4*)(g_h + (size_t)node * OUT_F + c16 * 8) = v;
        }
    }
}

// ---------------------------------------------------------------------------
// Scatter v3: pipelined cp.reduce.async.bulk.
// Block = 256 edges in 4 batches of 64, double-buffered smem (2 x 16 KB).
// Batch i gathers into buf[i&1] while batch i-1's TMA group is in flight;
// wait_group 1 before reusing a buffer (batch i-2 drained). The bulk-reduce
// completion latency overlaps the next batch's gather instead of being
// exposed once per 64 edges.
// ---------------------------------------------------------------------------
__global__ __launch_bounds__(256) void scatter_kernel(
    const int* __restrict__ esrc,
    const int* __restrict__ edst,
    const float* __restrict__ ew,
    float* __restrict__ out)
{
    __shared__ __align__(16) float sm[2][EPB * OUT_F];   // 2 x 16 KB

    const int tid = threadIdx.x;
    const int half_id = tid >> 4;     // 0..15
    const int lane16  = tid & 15;
    const int eblk = blockIdx.x * (EPB * NBATCH);

    #pragma unroll
    for (int bt = 0; bt < NBATCH; bt++) {
        float* buf = sm[bt & 1];
        const int e0 = eblk + bt * EPB;

        // Before overwriting this buffer, make sure batch bt-2's TMA is done.
        if (bt >= 2) {
            if (tid < EPB)
                asm volatile("cp.async.bulk.wait_group 1;" ::: "memory");
            __syncthreads();
        }

        // Gather + scale: each half-warp handles 4 edges.
        #pragma unroll
        for (int p = 0; p < 4; p++) {
            const int r = p * 16 + half_id;
            const int e = e0 + r;                 // N_EDGES % 256 == 0, no tail
            const int   s = esrc[e];              // broadcast within half-warp
            const float w = ew[e];

            const uint2 hraw = *(const uint2*)(g_h + (size_t)s * OUT_F + lane16 * 4);
            const float2 f0 = __half22float2(*(const __half2*)&hraw.x);
            const float2 f1 = __half22float2(*(const __half2*)&hraw.y);
            float4 hv = make_float4(f0.x * w, f0.y * w, f1.x * w, f1.y * w);
            *(float4*)&buf[r * OUT_F + lane16 * 4] = hv;
        }
        __syncthreads();

        // Issue one bulk atomic-add per edge row (threads 0..63), no wait.
        if (tid < EPB) {
            asm volatile("fence.proxy.async.shared::cta;" ::: "memory");
            const int d = edst[e0 + tid];
            float* dst = out + (size_t)d * OUT_F;          // 256 B aligned
            uint32_t src_smem;
            asm("{ .reg .u64 t; cvta.to.shared.u64 t, %1; cvt.u32.u64 %0, t; }"
                : "=r"(src_smem) : "l"(&buf[tid * OUT_F]));
            asm volatile(
                "cp.reduce.async.bulk.global.shared::cta.bulk_group.add.f32 "
                "[%0], [%1], %2;"
                :: "l"(dst), "r"(src_smem), "n"(OUT_F * 4)
                : "memory");
            asm volatile("cp.async.bulk.commit_group;" ::: "memory");
        }
    }

    // Drain all outstanding groups before smem is released.
    if (tid < EPB)
        asm volatile("cp.async.bulk.wait_group 0;" ::: "memory");
}

// ---------------------------------------------------------------------------
extern "C" void kernel_launch(void* const* d_in, const int* in_sizes, int n_in,
                              void* d_out, int out_size) {
    const float* feat = (const float*)d_in[0];
    const int*   esrc = (const int*)d_in[1];   // int32 (JAX x64 disabled)
    const int*   edst = (const int*)d_in[2];
    const float* ew   = (const float*)d_in[3];
    const float* W    = (const float*)d_in[4];
    const float* b    = (const float*)d_in[5];
    float* out = (float*)d_out;

    gemm_kernel<<<(N_NODES + 63) / 64, 256>>>(feat, W, b, (float4*)out);

    scatter_kernel<<<N_EDGES / (EPB * NBATCH), 256>>>(esrc, edst, ew, out);  // 3125 blocks
}

// round 11
// speedup vs baseline: 1.1356x; 1.1356x over previous
#include <cuda_runtime.h>
#include <cuda_fp16.h>
#include <stdint.h>

#define N_NODES 50000
#define N_EDGES 800000
#define IN_F    128
#define OUT_F   64

#define SA_STRIDE 136   // halves per smem row (128 + 8 pad -> conflict-free frags)
#define SH_STRIDE 72    // halves per epilogue staging row (64 + 8 pad)

// Scratch (allocation-free rule: __device__ globals)
__device__ __half g_h[(size_t)N_NODES * OUT_F];  // 6.4 MB fp16 h table (L2-resident)

// ---------------------------------------------------------------------------
// GEMM: h = feat @ W^T + b  via mma.sync m16n8k16 (fp16 in, fp32 accum).
// (unchanged — smem-staged coalesced epilogue). Side-job: zero `out`.
// ---------------------------------------------------------------------------
__global__ __launch_bounds__(256) void gemm_kernel(
    const float* __restrict__ feat,
    const float* __restrict__ W,
    const float* __restrict__ b,
    float4* __restrict__ out4)
{
    __shared__ __align__(16) __half sA[64 * SA_STRIDE];
    __shared__ __align__(16) __half sB[64 * SA_STRIDE];
    __shared__ float sBias[OUT_F];

    const int tid = threadIdx.x;
    const int node0 = blockIdx.x * 64;

    // Zero the output (independent side-job)
    {
        const int per_blk = (N_NODES * OUT_F / 4 + gridDim.x - 1) / gridDim.x;
        int base = blockIdx.x * per_blk;
        for (int i = tid; i < per_blk; i += 256) {
            int idx = base + i;
            if (idx < N_NODES * OUT_F / 4)
                out4[idx] = make_float4(0.f, 0.f, 0.f, 0.f);
        }
    }

    if (tid < OUT_F) sBias[tid] = b[tid];

    // Load W [64 x 128] fp32 -> fp16 smem
    {
        const float4* src = (const float4*)W;
        #pragma unroll
        for (int i = 0; i < 8; i++) {
            int idx = tid + i * 256;
            int o = idx >> 5, c4 = idx & 31;
            float4 v = src[idx];
            __half2 h01 = __floats2half2_rn(v.x, v.y);
            __half2 h23 = __floats2half2_rn(v.z, v.w);
            uint2 pk;
            pk.x = *(const unsigned int*)&h01;
            pk.y = *(const unsigned int*)&h23;
            *(uint2*)&sB[o * SA_STRIDE + c4 * 4] = pk;
        }
    }
    // Load 64 feat rows fp32 -> fp16 smem, zero-pad past N_NODES
    {
        const float4* src = (const float4*)feat;
        #pragma unroll
        for (int i = 0; i < 8; i++) {
            int idx = tid + i * 256;
            int n = idx >> 5, c4 = idx & 31;
            int node = node0 + n;
            float4 v = (node < N_NODES) ? src[(size_t)node * 32 + c4]
                                        : make_float4(0.f, 0.f, 0.f, 0.f);
            __half2 h01 = __floats2half2_rn(v.x, v.y);
            __half2 h23 = __floats2half2_rn(v.z, v.w);
            uint2 pk;
            pk.x = *(const unsigned int*)&h01;
            pk.y = *(const unsigned int*)&h23;
            *(uint2*)&sA[n * SA_STRIDE + c4 * 4] = pk;
        }
    }
    __syncthreads();

    const int lane = tid & 31;
    const int w    = tid >> 5;
    const int g    = lane >> 2;
    const int t    = lane & 3;
    const int mrow = (w >> 1) * 16;
    const int nbase = (w & 1) * 32;

    float c[4][4] = {};

    #pragma unroll
    for (int ks = 0; ks < 8; ks++) {
        const int k0 = ks * 16;
        const uint32_t a0 = *(const uint32_t*)&sA[(mrow + g    ) * SA_STRIDE + k0 + 2 * t];
        const uint32_t a1 = *(const uint32_t*)&sA[(mrow + g + 8) * SA_STRIDE + k0 + 2 * t];
        const uint32_t a2 = *(const uint32_t*)&sA[(mrow + g    ) * SA_STRIDE + k0 + 2 * t + 8];
        const uint32_t a3 = *(const uint32_t*)&sA[(mrow + g + 8) * SA_STRIDE + k0 + 2 * t + 8];
        #pragma unroll
        for (int nc = 0; nc < 4; nc++) {
            const int n = nbase + nc * 8 + g;
            const uint32_t b0 = *(const uint32_t*)&sB[n * SA_STRIDE + k0 + 2 * t];
            const uint32_t b1 = *(const uint32_t*)&sB[n * SA_STRIDE + k0 + 2 * t + 8];
            asm volatile(
                "mma.sync.aligned.m16n8k16.row.col.f32.f16.f16.f32 "
                "{%0,%1,%2,%3}, {%4,%5,%6,%7}, {%8,%9}, {%0,%1,%2,%3};"
                : "+f"(c[nc][0]), "+f"(c[nc][1]), "+f"(c[nc][2]), "+f"(c[nc][3])
                : "r"(a0), "r"(a1), "r"(a2), "r"(a3), "r"(b0), "r"(b1));
        }
    }

    // Epilogue: stage to smem (conflict-free), then coalesced uint4 STG
    __syncthreads();
    __half* sH = sA;
    #pragma unroll
    for (int nc = 0; nc < 4; nc++) {
        const int col = nbase + nc * 8 + 2 * t;
        const float b0f = sBias[col], b1f = sBias[col + 1];
        const __half2 h0 = __floats2half2_rn(c[nc][0] + b0f, c[nc][1] + b1f);
        const __half2 h1 = __floats2half2_rn(c[nc][2] + b0f, c[nc][3] + b1f);
        *(__half2*)&sH[(mrow + g    ) * SH_STRIDE + col] = h0;
        *(__half2*)&sH[(mrow + g + 8) * SH_STRIDE + col] = h1;
    }
    __syncthreads();
    #pragma unroll
    for (int i = 0; i < 2; i++) {
        int idx = tid + i * 256;
        int row = idx >> 3;
        int c16 = idx & 7;
        int node = node0 + row;
        if (node < N_NODES) {
            uint4 v = *(const uint4*)&sH[row * SH_STRIDE + c16 * 8];
            *(uint4*)(g_h + (size_t)node * OUT_F + c16 * 8) = v;
        }
    }
}

// ---------------------------------------------------------------------------
// Scatter v4: warp-autonomous cp.reduce.async.bulk. NO block-wide syncs.
// Block = 64 edges, warp owns 8 edge rows: each half-warp gathers 4 rows
// (MLP=4), one __syncwarp, then lanes 0..7 each fence+issue one 256 B bulk
// atomic-add, commit once, wait once. Warps issue as soon as THEIR rows are
// staged -> TMA in flight overlaps other warps' gathers.
// ---------------------------------------------------------------------------
__global__ __launch_bounds__(256) void scatter_kernel(
    const int* __restrict__ esrc,
    const int* __restrict__ edst,
    const float* __restrict__ ew,
    float* __restrict__ out)
{
    __shared__ __align__(16) float sm[64 * OUT_F];   // 16 KB: 64 edge rows

    const int tid  = threadIdx.x;
    const int warp = tid >> 5;            // 0..7, owns rows [warp*8, warp*8+8)
    const int lane = tid & 31;
    const int half = (tid >> 4) & 1;      // half-warp within warp
    const int lane16 = tid & 15;
    const int e0 = blockIdx.x * 64;       // N_EDGES % 64 == 0, no tail

    // Gather + scale: half-warp handles rows warp*8 + p*2 + half (4 rows, MLP=4)
    #pragma unroll
    for (int p = 0; p < 4; p++) {
        const int r = warp * 8 + p * 2 + half;
        const int e = e0 + r;
        const int   s = esrc[e];              // broadcast within half-warp
        const float w = ew[e];

        const uint2 hraw = *(const uint2*)(g_h + (size_t)s * OUT_F + lane16 * 4);
        const float2 f0 = __half22float2(*(const __half2*)&hraw.x);
        const float2 f1 = __half22float2(*(const __half2*)&hraw.y);
        float4 hv = make_float4(f0.x * w, f0.y * w, f1.x * w, f1.y * w);
        *(float4*)&sm[r * OUT_F + lane16 * 4] = hv;
    }
    __syncwarp();    // my warp's 8 rows staged (happens-before for the fence)

    // Lanes 0..7: one bulk atomic-add each for rows warp*8 + lane.
    if (lane < 8) {
        asm volatile("fence.proxy.async.shared::cta;" ::: "memory");
        const int r = warp * 8 + lane;
        const int d = edst[e0 + r];
        float* dst = out + (size_t)d * OUT_F;          // 256 B aligned
        uint32_t src_smem;
        asm("{ .reg .u64 t; cvta.to.shared.u64 t, %1; cvt.u32.u64 %0, t; }"
            : "=r"(src_smem) : "l"(&sm[r * OUT_F]));
        asm volatile(
            "cp.reduce.async.bulk.global.shared::cta.bulk_group.add.f32 "
            "[%0], [%1], %2;"
            :: "l"(dst), "r"(src_smem), "n"(OUT_F * 4)
            : "memory");
        asm volatile("cp.async.bulk.commit_group;" ::: "memory");
        asm volatile("cp.async.bulk.wait_group 0;" ::: "memory");
    }
}

// ---------------------------------------------------------------------------
extern "C" void kernel_launch(void* const* d_in, const int* in_sizes, int n_in,
                              void* d_out, int out_size) {
    const float* feat = (const float*)d_in[0];
    const int*   esrc = (const int*)d_in[1];   // int32 (JAX x64 disabled)
    const int*   edst = (const int*)d_in[2];
    const float* ew   = (const float*)d_in[3];
    const float* W    = (const float*)d_in[4];
    const float* b    = (const float*)d_in[5];
    float* out = (float*)d_out;

    gemm_kernel<<<(N_NODES + 63) / 64, 256>>>(feat, W, b, (float4*)out);

    scatter_kernel<<<N_EDGES / 64, 256>>>(esrc, edst, ew, out);   // 12500 blocks
}